// round 8
// baseline (speedup 1.0000x reference)
#include <cuda_runtime.h>
#include <math_constants.h>

// ZBLRepulsion fused: E = sum_edges 0.5*Zi*Zj/dr * f(dist) * cos_cutoff(dr)
// Single gather kernel: d2<36 filter (cos_cutoff==0 beyond), predicated math,
// block reduce, done-counter finalize.
// EPT=4 + launch_bounds(256,6): target ~42 regs -> 6 CTAs/SM (75% occ) to
// cover L1/L2 gather latency; L1tex wavefront throughput is the floor.

#define N_ATOMS_MAX 100032
#define EPT 4  // edges per thread

__device__ float4 g_P[N_ATOMS_MAX];   // {x, y, z, Z_as_int_bits}
__device__ float  g_pow[64];          // z^a_exp
__device__ double g_acc;
__device__ int    g_done;

// ---------------------------------------------------------------------------
__global__ void prep_kernel(const float* __restrict__ R,
                            const int* __restrict__ Z,
                            const float* __restrict__ a_exp,
                            int n_atoms) {
    int tid = blockIdx.x * blockDim.x + threadIdx.x;
    if (tid < 64) g_pow[tid] = powf((float)tid, a_exp[0]);
    if (tid == 0) { g_acc = 0.0; g_done = 0; }
    int stride = gridDim.x * blockDim.x;
    for (int i = tid; i < n_atoms; i += stride) {
        float4 p;
        p.x = R[3 * i + 0];
        p.y = R[3 * i + 1];
        p.z = R[3 * i + 2];
        p.w = __int_as_float(Z[i]);
        g_P[i] = p;
    }
}

// ---------------------------------------------------------------------------
__global__ void __launch_bounds__(256, 6)
main_kernel(const int* __restrict__ idx, int n_edges, int n_atoms,
            const float* __restrict__ a_num,
            const float* __restrict__ coef,
            const float* __restrict__ expo,
            float* __restrict__ out) {
    __shared__ float s_pow[64];
    __shared__ float s_red[8];
    __shared__ bool  s_last;
    if (threadIdx.x < 64) s_pow[threadIdx.x] = g_pow[threadIdx.x];
    __syncthreads();

    int t  = blockIdx.x * blockDim.x + threadIdx.x;
    int e0 = t * EPT;

    int is[EPT], js[EPT];
    if (e0 + EPT - 1 < n_edges) {
        int4 a = __ldcs(reinterpret_cast<const int4*>(idx + e0));
        int4 c = __ldcs(reinterpret_cast<const int4*>(idx + n_edges + e0));
        is[0]=a.x; is[1]=a.y; is[2]=a.z; is[3]=a.w;
        js[0]=c.x; js[1]=c.y; js[2]=c.z; js[3]=c.w;
    } else {
#pragma unroll
        for (int k = 0; k < EPT; k++) {
            int e = e0 + k;
            is[k] = (e < n_edges) ? idx[e] : -1;
            js[k] = (e < n_edges) ? idx[n_edges + e] : -1;
        }
    }

    // gather + d2; pack zi|zj<<8 to keep live state small
    float d2v[EPT];
    int   zzv[EPT];
#pragma unroll
    for (int k = 0; k < EPT; k++) {
        int i = is[k], j = js[k];
        bool valid = ((unsigned)i < (unsigned)n_atoms) & ((unsigned)j < (unsigned)n_atoms);
        float d2 = 1e30f; int zz = 0;
        if (valid) {
            float4 pi = g_P[i];
            float4 pj = g_P[j];
            float dx = pj.x - pi.x;
            float dy = pj.y - pi.y;
            float dz = pj.z - pi.z;
            d2 = fmaf(dx, dx, fmaf(dy, dy, dz * dz));
            zz = __float_as_int(pi.w) | (__float_as_int(pj.w) << 8);
        }
        d2v[k] = d2; zzv[k] = zz;
    }

    float inv_anum = 1.0f / a_num[0];
    float c0 = coef[0], c1 = coef[1], c2 = coef[2], c3 = coef[3];
    float x0 = expo[0], x1 = expo[1], x2 = expo[2], x3 = expo[3];

    float acc = 0.0f;
#pragma unroll
    for (int k = 0; k < EPT; k++) {
        float d2 = d2v[k];
        if (d2 < 36.0f) {                       // beyond: cos_cutoff == 0 exactly
            int zi = zzv[k] & 0xff;
            int zj = (zzv[k] >> 8) & 0xff;
            d2 = fmaxf(d2, 4e-4f);              // lower clip dr>=0.02 (in d2 domain; no rsqrt(0) NaN)
            float inv_dr = rsqrtf(d2);
            float dr = d2 * inv_dr;             // == sqrt(d2), in [0.02, 6)
            float cut = 0.5f * (__cosf((CUDART_PI_F / 6.0f) * dr) + 1.0f);
            float dist = dr * (s_pow[zi] + s_pow[zj]) * inv_anum;
            float f = c0 * __expf(-x0 * dist)
                    + c1 * __expf(-x1 * dist)
                    + c2 * __expf(-x2 * dist)
                    + c3 * __expf(-x3 * dist);
            acc += 0.5f * (float)(zi * zj) * f * cut * inv_dr;
        }
    }

    // block reduction
#pragma unroll
    for (int o = 16; o > 0; o >>= 1)
        acc += __shfl_down_sync(0xffffffffu, acc, o);
    int wid = threadIdx.x >> 5;
    if ((threadIdx.x & 31) == 0) s_red[wid] = acc;
    __syncthreads();
    if (threadIdx.x == 0) {
        float v = 0.0f;
#pragma unroll
        for (int w = 0; w < 8; w++) v += s_red[w];
        if (v != 0.0f) atomicAdd(&g_acc, (double)v);
        __threadfence();
        int done = atomicAdd(&g_done, 1);
        s_last = (done == (int)gridDim.x - 1);
    }
    __syncthreads();
    if (s_last && threadIdx.x == 0) {
        double total = *((volatile double*)&g_acc);
        out[0] = (float)total;
    }
}

// ---------------------------------------------------------------------------
extern "C" void kernel_launch(void* const* d_in, const int* in_sizes, int n_in,
                              void* d_out, int out_size) {
    const float* R      = (const float*)d_in[0];
    const int*   Z      = (const int*)d_in[1];
    const int*   idx    = (const int*)d_in[2];
    const float* a_exp  = (const float*)d_in[3];
    const float* a_num  = (const float*)d_in[4];
    const float* coef   = (const float*)d_in[5];
    const float* expo   = (const float*)d_in[6];
    float* out = (float*)d_out;

    int n_atoms = in_sizes[1];
    if (n_atoms > N_ATOMS_MAX) n_atoms = N_ATOMS_MAX;
    int n_edges = in_sizes[2] / 2;

    int prep_blocks = (n_atoms + 255) / 256;
    prep_kernel<<<prep_blocks, 256>>>(R, Z, a_exp, n_atoms);

    int n_threads = (n_edges + EPT - 1) / EPT;
    int blocks = (n_threads + 255) / 256;
    main_kernel<<<blocks, 256>>>(idx, n_edges, n_atoms, a_num, coef, expo, out);
}

// round 9
// speedup vs baseline: 1.1303x; 1.1303x over previous
#include <cuda_runtime.h>
#include <math_constants.h>

// ZBLRepulsion fused: E = sum_edges 0.5*Zi*Zj/dr * f(dist) * cos_cutoff(dr)
// Persistent gather kernel: 592 CTAs grid-stride over 2048-edge chunks.
// EPT=8 + 4 CTAs/SM = 512 outstanding gathers/SM (measured optimum).
// d2<36 filter (cos_cutoff==0 beyond), d2-domain lower clip (no rsqrt(0) NaN),
// one block reduction + one double atomic per CTA at the end.

#define N_ATOMS_MAX 100032
#define EPT 8          // edges per thread per chunk
#define TPB 256
#define CHUNK (TPB * EPT)   // 2048 edges per chunk
#define N_CTAS 592          // 148 SMs * 4 CTAs

__device__ float4 g_P[N_ATOMS_MAX];   // {x, y, z, Z_as_int_bits}
__device__ float  g_pow[64];          // z^a_exp
__device__ double g_acc;
__device__ int    g_done;

// ---------------------------------------------------------------------------
__global__ void prep_kernel(const float* __restrict__ R,
                            const int* __restrict__ Z,
                            const float* __restrict__ a_exp,
                            int n_atoms) {
    int tid = blockIdx.x * blockDim.x + threadIdx.x;
    if (tid < 64) g_pow[tid] = powf((float)tid, a_exp[0]);
    if (tid == 0) { g_acc = 0.0; g_done = 0; }
    int stride = gridDim.x * blockDim.x;
    for (int i = tid; i < n_atoms; i += stride) {
        float4 p;
        p.x = R[3 * i + 0];
        p.y = R[3 * i + 1];
        p.z = R[3 * i + 2];
        p.w = __int_as_float(Z[i]);
        g_P[i] = p;
    }
}

// ---------------------------------------------------------------------------
__global__ void __launch_bounds__(TPB, 4)
main_kernel(const int* __restrict__ idx, int n_edges, int n_atoms,
            const float* __restrict__ a_num,
            const float* __restrict__ coef,
            const float* __restrict__ expo,
            float* __restrict__ out) {
    __shared__ float s_pow[64];
    __shared__ float s_red[8];
    __shared__ bool  s_last;
    if (threadIdx.x < 64) s_pow[threadIdx.x] = g_pow[threadIdx.x];
    __syncthreads();

    float inv_anum = 1.0f / a_num[0];
    float c0 = coef[0], c1 = coef[1], c2 = coef[2], c3 = coef[3];
    float x0 = expo[0], x1 = expo[1], x2 = expo[2], x3 = expo[3];

    int n_chunks = (n_edges + CHUNK - 1) / CHUNK;
    float acc = 0.0f;

    for (int chunk = blockIdx.x; chunk < n_chunks; chunk += gridDim.x) {
        int e0 = chunk * CHUNK + threadIdx.x * EPT;

        int is[EPT], js[EPT];
        if (e0 + EPT - 1 < n_edges) {
            const int4* pi4 = reinterpret_cast<const int4*>(idx + e0);
            const int4* pj4 = reinterpret_cast<const int4*>(idx + n_edges + e0);
            int4 a = __ldcs(pi4 + 0), b = __ldcs(pi4 + 1);
            int4 c = __ldcs(pj4 + 0), d = __ldcs(pj4 + 1);
            is[0]=a.x; is[1]=a.y; is[2]=a.z; is[3]=a.w;
            is[4]=b.x; is[5]=b.y; is[6]=b.z; is[7]=b.w;
            js[0]=c.x; js[1]=c.y; js[2]=c.z; js[3]=c.w;
            js[4]=d.x; js[5]=d.y; js[6]=d.z; js[7]=d.w;
        } else {
#pragma unroll
            for (int k = 0; k < EPT; k++) {
                int e = e0 + k;
                is[k] = (e < n_edges) ? idx[e] : -1;
                js[k] = (e < n_edges) ? idx[n_edges + e] : -1;
            }
        }

        // gather + d2; pack zi|zj<<8 (front-batched loads for MLP)
        float d2v[EPT];
        int   zzv[EPT];
#pragma unroll
        for (int k = 0; k < EPT; k++) {
            int i = is[k], j = js[k];
            bool valid = ((unsigned)i < (unsigned)n_atoms) & ((unsigned)j < (unsigned)n_atoms);
            float d2 = 1e30f; int zz = 0;
            if (valid) {
                float4 pi = g_P[i];
                float4 pj = g_P[j];
                float dx = pj.x - pi.x;
                float dy = pj.y - pi.y;
                float dz = pj.z - pi.z;
                d2 = fmaf(dx, dx, fmaf(dy, dy, dz * dz));
                zz = __float_as_int(pi.w) | (__float_as_int(pj.w) << 8);
            }
            d2v[k] = d2; zzv[k] = zz;
        }

#pragma unroll
        for (int k = 0; k < EPT; k++) {
            float d2 = d2v[k];
            if (d2 < 36.0f) {                   // beyond: cos_cutoff == 0 exactly
                int zi = zzv[k] & 0xff;
                int zj = (zzv[k] >> 8) & 0xff;
                d2 = fmaxf(d2, 4e-4f);          // lower clip dr>=0.02 in d2 domain
                float inv_dr = rsqrtf(d2);
                float dr = d2 * inv_dr;         // == sqrt(d2), in [0.02, 6)
                float cut = 0.5f * (__cosf((CUDART_PI_F / 6.0f) * dr) + 1.0f);
                float dist = dr * (s_pow[zi] + s_pow[zj]) * inv_anum;
                float f = c0 * __expf(-x0 * dist)
                        + c1 * __expf(-x1 * dist)
                        + c2 * __expf(-x2 * dist)
                        + c3 * __expf(-x3 * dist);
                acc += 0.5f * (float)(zi * zj) * f * cut * inv_dr;
            }
        }
    }

    // one block reduction + one atomic per CTA
#pragma unroll
    for (int o = 16; o > 0; o >>= 1)
        acc += __shfl_down_sync(0xffffffffu, acc, o);
    int wid = threadIdx.x >> 5;
    if ((threadIdx.x & 31) == 0) s_red[wid] = acc;
    __syncthreads();
    if (threadIdx.x == 0) {
        float v = 0.0f;
#pragma unroll
        for (int w = 0; w < 8; w++) v += s_red[w];
        if (v != 0.0f) atomicAdd(&g_acc, (double)v);
        __threadfence();
        int done = atomicAdd(&g_done, 1);
        s_last = (done == (int)gridDim.x - 1);
    }
    __syncthreads();
    if (s_last && threadIdx.x == 0) {
        double total = *((volatile double*)&g_acc);
        out[0] = (float)total;
    }
}

// ---------------------------------------------------------------------------
extern "C" void kernel_launch(void* const* d_in, const int* in_sizes, int n_in,
                              void* d_out, int out_size) {
    const float* R      = (const float*)d_in[0];
    const int*   Z      = (const int*)d_in[1];
    const int*   idx    = (const int*)d_in[2];
    const float* a_exp  = (const float*)d_in[3];
    const float* a_num  = (const float*)d_in[4];
    const float* coef   = (const float*)d_in[5];
    const float* expo   = (const float*)d_in[6];
    float* out = (float*)d_out;

    int n_atoms = in_sizes[1];
    if (n_atoms > N_ATOMS_MAX) n_atoms = N_ATOMS_MAX;
    int n_edges = in_sizes[2] / 2;

    int prep_blocks = (n_atoms + 255) / 256;
    prep_kernel<<<prep_blocks, 256>>>(R, Z, a_exp, n_atoms);

    int n_chunks = (n_edges + CHUNK - 1) / CHUNK;
    int blocks = N_CTAS < n_chunks ? N_CTAS : n_chunks;
    main_kernel<<<blocks, TPB>>>(idx, n_edges, n_atoms, a_num, coef, expo, out);
}

// round 10
// speedup vs baseline: 1.1357x; 1.0048x over previous
#include <cuda_runtime.h>
#include <math_constants.h>

// ZBLRepulsion fused: E = sum_edges 0.5*Zi*Zj/dr * f(dist) * cos_cutoff(dr)
// Persistent gather kernel, software-pipelined:
//   per chunk: [gathers issue] -> [prefetch NEXT chunk idx into dead is/js regs]
//              -> [transcendental math] ; idx latency overlaps gather+math.
// EPT=8 + 4 CTAs/SM = 512 outstanding gathers/SM (measured optimum).
// d2<36 filter (cos_cutoff==0 beyond), d2-domain lower clip (no rsqrt(0) NaN).

#define N_ATOMS_MAX 100032
#define EPT 8          // edges per thread per chunk
#define TPB 256
#define CHUNK (TPB * EPT)   // 2048 edges per chunk
#define N_CTAS 592          // 148 SMs * 4 CTAs

__device__ float4 g_P[N_ATOMS_MAX];   // {x, y, z, Z_as_int_bits}
__device__ float  g_pow[64];          // z^a_exp
__device__ double g_acc;
__device__ int    g_done;

// ---------------------------------------------------------------------------
__global__ void prep_kernel(const float* __restrict__ R,
                            const int* __restrict__ Z,
                            const float* __restrict__ a_exp,
                            int n_atoms) {
    int tid = blockIdx.x * blockDim.x + threadIdx.x;
    if (tid < 64) g_pow[tid] = powf((float)tid, a_exp[0]);
    if (tid == 0) { g_acc = 0.0; g_done = 0; }
    int stride = gridDim.x * blockDim.x;
    for (int i = tid; i < n_atoms; i += stride) {
        float4 p;
        p.x = R[3 * i + 0];
        p.y = R[3 * i + 1];
        p.z = R[3 * i + 2];
        p.w = __int_as_float(Z[i]);
        g_P[i] = p;
    }
}

// ---------------------------------------------------------------------------
__device__ __forceinline__ void load_idx(const int* __restrict__ idx,
                                         int n_edges, int e0,
                                         int* is, int* js) {
    if (e0 + EPT - 1 < n_edges) {
        const int4* pi4 = reinterpret_cast<const int4*>(idx + e0);
        const int4* pj4 = reinterpret_cast<const int4*>(idx + n_edges + e0);
        int4 a = __ldcs(pi4 + 0), b = __ldcs(pi4 + 1);
        int4 c = __ldcs(pj4 + 0), d = __ldcs(pj4 + 1);
        is[0]=a.x; is[1]=a.y; is[2]=a.z; is[3]=a.w;
        is[4]=b.x; is[5]=b.y; is[6]=b.z; is[7]=b.w;
        js[0]=c.x; js[1]=c.y; js[2]=c.z; js[3]=c.w;
        js[4]=d.x; js[5]=d.y; js[6]=d.z; js[7]=d.w;
    } else {
#pragma unroll
        for (int k = 0; k < EPT; k++) {
            int e = e0 + k;
            is[k] = (e < n_edges) ? idx[e] : -1;
            js[k] = (e < n_edges) ? idx[n_edges + e] : -1;
        }
    }
}

// ---------------------------------------------------------------------------
__global__ void __launch_bounds__(TPB, 4)
main_kernel(const int* __restrict__ idx, int n_edges, int n_atoms,
            const float* __restrict__ a_num,
            const float* __restrict__ coef,
            const float* __restrict__ expo,
            float* __restrict__ out) {
    __shared__ float s_pow[64];
    __shared__ float s_red[8];
    __shared__ bool  s_last;
    if (threadIdx.x < 64) s_pow[threadIdx.x] = g_pow[threadIdx.x];
    __syncthreads();

    float inv_anum = 1.0f / a_num[0];
    float c0 = coef[0], c1 = coef[1], c2 = coef[2], c3 = coef[3];
    float x0 = expo[0], x1 = expo[1], x2 = expo[2], x3 = expo[3];

    int n_chunks = (n_edges + CHUNK - 1) / CHUNK;
    float acc = 0.0f;

    int is[EPT], js[EPT];
    int chunk = blockIdx.x;
    if (chunk < n_chunks)
        load_idx(idx, n_edges, chunk * CHUNK + threadIdx.x * EPT, is, js);

    for (; chunk < n_chunks; chunk += gridDim.x) {
        // gather + d2; pack zi|zj<<8 (front-batched loads for MLP)
        float d2v[EPT];
        int   zzv[EPT];
#pragma unroll
        for (int k = 0; k < EPT; k++) {
            int i = is[k], j = js[k];
            bool valid = ((unsigned)i < (unsigned)n_atoms) & ((unsigned)j < (unsigned)n_atoms);
            float d2 = 1e30f; int zz = 0;
            if (valid) {
                float4 pi = g_P[i];
                float4 pj = g_P[j];
                float dx = pj.x - pi.x;
                float dy = pj.y - pi.y;
                float dz = pj.z - pi.z;
                d2 = fmaf(dx, dx, fmaf(dy, dy, dz * dz));
                zz = __float_as_int(pi.w) | (__float_as_int(pj.w) << 8);
            }
            d2v[k] = d2; zzv[k] = zz;
        }

        // prefetch NEXT chunk's indices into the now-dead is/js registers;
        // these loads overlap the gather scoreboard waits and the math below.
        int next = chunk + gridDim.x;
        if (next < n_chunks)
            load_idx(idx, n_edges, next * CHUNK + threadIdx.x * EPT, is, js);

#pragma unroll
        for (int k = 0; k < EPT; k++) {
            float d2 = d2v[k];
            if (d2 < 36.0f) {                   // beyond: cos_cutoff == 0 exactly
                int zi = zzv[k] & 0xff;
                int zj = (zzv[k] >> 8) & 0xff;
                d2 = fmaxf(d2, 4e-4f);          // lower clip dr>=0.02 in d2 domain
                float inv_dr = rsqrtf(d2);
                float dr = d2 * inv_dr;         // == sqrt(d2), in [0.02, 6)
                float cut = 0.5f * (__cosf((CUDART_PI_F / 6.0f) * dr) + 1.0f);
                float dist = dr * (s_pow[zi] + s_pow[zj]) * inv_anum;
                float f = c0 * __expf(-x0 * dist)
                        + c1 * __expf(-x1 * dist)
                        + c2 * __expf(-x2 * dist)
                        + c3 * __expf(-x3 * dist);
                acc += 0.5f * (float)(zi * zj) * f * cut * inv_dr;
            }
        }
    }

    // one block reduction + one atomic per CTA
#pragma unroll
    for (int o = 16; o > 0; o >>= 1)
        acc += __shfl_down_sync(0xffffffffu, acc, o);
    int wid = threadIdx.x >> 5;
    if ((threadIdx.x & 31) == 0) s_red[wid] = acc;
    __syncthreads();
    if (threadIdx.x == 0) {
        float v = 0.0f;
#pragma unroll
        for (int w = 0; w < 8; w++) v += s_red[w];
        if (v != 0.0f) atomicAdd(&g_acc, (double)v);
        __threadfence();
        int done = atomicAdd(&g_done, 1);
        s_last = (done == (int)gridDim.x - 1);
    }
    __syncthreads();
    if (s_last && threadIdx.x == 0) {
        double total = *((volatile double*)&g_acc);
        out[0] = (float)total;
    }
}

// ---------------------------------------------------------------------------
extern "C" void kernel_launch(void* const* d_in, const int* in_sizes, int n_in,
                              void* d_out, int out_size) {
    const float* R      = (const float*)d_in[0];
    const int*   Z      = (const int*)d_in[1];
    const int*   idx    = (const int*)d_in[2];
    const float* a_exp  = (const float*)d_in[3];
    const float* a_num  = (const float*)d_in[4];
    const float* coef   = (const float*)d_in[5];
    const float* expo   = (const float*)d_in[6];
    float* out = (float*)d_out;

    int n_atoms = in_sizes[1];
    if (n_atoms > N_ATOMS_MAX) n_atoms = N_ATOMS_MAX;
    int n_edges = in_sizes[2] / 2;

    int prep_blocks = (n_atoms + 255) / 256;
    prep_kernel<<<prep_blocks, 256>>>(R, Z, a_exp, n_atoms);

    int n_chunks = (n_edges + CHUNK - 1) / CHUNK;
    int blocks = N_CTAS < n_chunks ? N_CTAS : n_chunks;
    main_kernel<<<blocks, TPB>>>(idx, n_edges, n_atoms, a_num, coef, expo, out);
}

// round 16
// speedup vs baseline: 1.1508x; 1.0133x over previous
#include <cuda_runtime.h>
#include <math_constants.h>

// ZBLRepulsion fused: E = sum_edges 0.5*Zi*Zj/dr * f(dist) * cos_cutoff(dr)
// Persistent software-pipelined gather kernel.
// TPB=128, 8 CTAs/SM (same 32 warps/SM as before, finer scheduling grain),
// EPT=8 -> 16 outstanding gathers/thread (measured-optimal MLP shape).
// d2<36 filter (cos_cutoff==0 beyond), d2-domain lower clip (no rsqrt(0) NaN).

#define N_ATOMS_MAX 100032
#define EPT 8           // edges per thread per chunk
#define TPB 128
#define CHUNK (TPB * EPT)    // 1024 edges per chunk
#define N_CTAS 1184          // 148 SMs * 8 CTAs

__device__ float4 g_P[N_ATOMS_MAX];   // {x, y, z, Z_as_int_bits}
__device__ float  g_pow[64];          // z^a_exp
__device__ double g_acc;
__device__ int    g_done;

// ---------------------------------------------------------------------------
__global__ void prep_kernel(const float* __restrict__ R,
                            const int* __restrict__ Z,
                            const float* __restrict__ a_exp,
                            int n_atoms) {
    int tid = blockIdx.x * blockDim.x + threadIdx.x;
    if (tid < 64) g_pow[tid] = powf((float)tid, a_exp[0]);
    if (tid == 0) { g_acc = 0.0; g_done = 0; }
    int stride = gridDim.x * blockDim.x;
    for (int i = tid; i < n_atoms; i += stride) {
        float4 p;
        p.x = R[3 * i + 0];
        p.y = R[3 * i + 1];
        p.z = R[3 * i + 2];
        p.w = __int_as_float(Z[i]);
        g_P[i] = p;
    }
}

// ---------------------------------------------------------------------------
__device__ __forceinline__ void load_idx(const int* __restrict__ idx,
                                         int n_edges, int e0,
                                         int* is, int* js) {
    if (e0 + EPT - 1 < n_edges) {
        const int4* pi4 = reinterpret_cast<const int4*>(idx + e0);
        const int4* pj4 = reinterpret_cast<const int4*>(idx + n_edges + e0);
        int4 a = __ldcs(pi4 + 0), b = __ldcs(pi4 + 1);
        int4 c = __ldcs(pj4 + 0), d = __ldcs(pj4 + 1);
        is[0]=a.x; is[1]=a.y; is[2]=a.z; is[3]=a.w;
        is[4]=b.x; is[5]=b.y; is[6]=b.z; is[7]=b.w;
        js[0]=c.x; js[1]=c.y; js[2]=c.z; js[3]=c.w;
        js[4]=d.x; js[5]=d.y; js[6]=d.z; js[7]=d.w;
    } else {
#pragma unroll
        for (int k = 0; k < EPT; k++) {
            int e = e0 + k;
            is[k] = (e < n_edges) ? idx[e] : -1;
            js[k] = (e < n_edges) ? idx[n_edges + e] : -1;
        }
    }
}

// ---------------------------------------------------------------------------
__global__ void __launch_bounds__(TPB, 8)
main_kernel(const int* __restrict__ idx, int n_edges, int n_atoms,
            const float* __restrict__ a_num,
            const float* __restrict__ coef,
            const float* __restrict__ expo,
            float* __restrict__ out) {
    __shared__ float s_pow[64];
    __shared__ float s_red[4];
    __shared__ bool  s_last;
    if (threadIdx.x < 64) s_pow[threadIdx.x] = g_pow[threadIdx.x];
    __syncthreads();

    float inv_anum = 1.0f / a_num[0];
    float c0 = coef[0], c1 = coef[1], c2 = coef[2], c3 = coef[3];
    float x0 = expo[0], x1 = expo[1], x2 = expo[2], x3 = expo[3];

    int n_chunks = (n_edges + CHUNK - 1) / CHUNK;
    float acc = 0.0f;

    int is[EPT], js[EPT];
    int chunk = blockIdx.x;
    if (chunk < n_chunks)
        load_idx(idx, n_edges, chunk * CHUNK + threadIdx.x * EPT, is, js);

    for (; chunk < n_chunks; chunk += gridDim.x) {
        // gather + d2; pack zi|zj<<8 (front-batched loads for MLP)
        float d2v[EPT];
        int   zzv[EPT];
#pragma unroll
        for (int k = 0; k < EPT; k++) {
            int i = is[k], j = js[k];
            bool valid = ((unsigned)i < (unsigned)n_atoms) & ((unsigned)j < (unsigned)n_atoms);
            float d2 = 1e30f; int zz = 0;
            if (valid) {
                float4 pi = g_P[i];
                float4 pj = g_P[j];
                float dx = pj.x - pi.x;
                float dy = pj.y - pi.y;
                float dz = pj.z - pi.z;
                d2 = fmaf(dx, dx, fmaf(dy, dy, dz * dz));
                zz = __float_as_int(pi.w) | (__float_as_int(pj.w) << 8);
            }
            d2v[k] = d2; zzv[k] = zz;
        }

        // prefetch NEXT chunk's indices into the now-dead is/js registers;
        // overlaps the gather scoreboard waits and the math below.
        int next = chunk + gridDim.x;
        if (next < n_chunks)
            load_idx(idx, n_edges, next * CHUNK + threadIdx.x * EPT, is, js);

#pragma unroll
        for (int k = 0; k < EPT; k++) {
            float d2 = d2v[k];
            if (d2 < 36.0f) {                   // beyond: cos_cutoff == 0 exactly
                int zi = zzv[k] & 0xff;
                int zj = (zzv[k] >> 8) & 0xff;
                d2 = fmaxf(d2, 4e-4f);          // lower clip dr>=0.02 in d2 domain
                float inv_dr = rsqrtf(d2);
                float dr = d2 * inv_dr;         // == sqrt(d2), in [0.02, 6)
                float cut = 0.5f * (__cosf((CUDART_PI_F / 6.0f) * dr) + 1.0f);
                float dist = dr * (s_pow[zi] + s_pow[zj]) * inv_anum;
                float f = c0 * __expf(-x0 * dist)
                        + c1 * __expf(-x1 * dist)
                        + c2 * __expf(-x2 * dist)
                        + c3 * __expf(-x3 * dist);
                acc += 0.5f * (float)(zi * zj) * f * cut * inv_dr;
            }
        }
    }

    // one block reduction + one atomic per CTA
#pragma unroll
    for (int o = 16; o > 0; o >>= 1)
        acc += __shfl_down_sync(0xffffffffu, acc, o);
    int wid = threadIdx.x >> 5;
    if ((threadIdx.x & 31) == 0) s_red[wid] = acc;
    __syncthreads();
    if (threadIdx.x == 0) {
        float v = s_red[0] + s_red[1] + s_red[2] + s_red[3];
        if (v != 0.0f) atomicAdd(&g_acc, (double)v);
        __threadfence();
        int done = atomicAdd(&g_done, 1);
        s_last = (done == (int)gridDim.x - 1);
    }
    __syncthreads();
    if (s_last && threadIdx.x == 0) {
        double total = *((volatile double*)&g_acc);
        out[0] = (float)total;
    }
}

// ---------------------------------------------------------------------------
extern "C" void kernel_launch(void* const* d_in, const int* in_sizes, int n_in,
                              void* d_out, int out_size) {
    const float* R      = (const float*)d_in[0];
    const int*   Z      = (const int*)d_in[1];
    const int*   idx    = (const int*)d_in[2];
    const float* a_exp  = (const float*)d_in[3];
    const float* a_num  = (const float*)d_in[4];
    const float* coef   = (const float*)d_in[5];
    const float* expo   = (const float*)d_in[6];
    float* out = (float*)d_out;

    int n_atoms = in_sizes[1];
    if (n_atoms > N_ATOMS_MAX) n_atoms = N_ATOMS_MAX;
    int n_edges = in_sizes[2] / 2;

    int prep_blocks = (n_atoms + 255) / 256;
    prep_kernel<<<prep_blocks, 256>>>(R, Z, a_exp, n_atoms);

    int n_chunks = (n_edges + CHUNK - 1) / CHUNK;
    int blocks = N_CTAS < n_chunks ? N_CTAS : n_chunks;
    main_kernel<<<blocks, TPB>>>(idx, n_edges, n_atoms, a_num, coef, expo, out);
}